// round 1
// baseline (speedup 1.0000x reference)
#include <cuda_runtime.h>
#include <math.h>

#define VOCAB   32000
#define V4      (VOCAB / 4)      // 8000 float4 per row
#define NROWS   4092             // 4 * 1023
#define SEQ     1024
#define TPB     512              // threads per block in main kernel
#define FULL_K  (V4 / TPB)       // 15 full strided iterations
#define TAIL_N  (V4 - FULL_K * TPB)  // 320 tail elements

__device__ float  g_usum;
__device__ float  g_C1;
__device__ double g_acc;

// Fast natural log via bit-twiddle range reduction + degree-6 Taylor.
// Valid for any positive normal float. |abs err| <= ~9e-5 over the full range.
// m in [2/3, 4/3), f = m-1 in [-1/3, 1/3), ln(x) = f*P(f) + k * ln2/2^23.
__device__ __forceinline__ float lnfast(float x) {
    int i = __float_as_int(x);
    int k = (i - 0x3F2AAAAB) & 0xFF800000;
    float f = __int_as_float(i - k) - 1.0f;
    float P = -0.16666667f;              // Taylor coeffs of ln(1+f)/f
    P = fmaf(P, f,  0.2f);
    P = fmaf(P, f, -0.25f);
    P = fmaf(P, f,  0.33333334f);
    P = fmaf(P, f, -0.5f);
    P = fmaf(P, f,  1.0f);
    return fmaf(f, P, (float)k * 8.2629582e-8f);  // ln2 / 2^23
}

__device__ __forceinline__ float warp_sum(float v) {
    #pragma unroll
    for (int o = 16; o; o >>= 1) v += __shfl_xor_sync(0xFFFFFFFFu, v, o);
    return v;
}

// One block: usum = sum(th), C1 = sum f(eps*th/usum), zero accumulator.
__global__ void prep_kernel(const float* __restrict__ th) {
    __shared__ float red[32];
    __shared__ float s_usum;
    const int tid = threadIdx.x;
    const int nw  = blockDim.x >> 5;

    float s = 0.f;
    for (int i = tid; i < VOCAB; i += blockDim.x) s += th[i];
    s = warp_sum(s);
    if ((tid & 31) == 0) red[tid >> 5] = s;
    __syncthreads();
    if (tid == 0) {
        float t = 0.f;
        for (int w = 0; w < nw; w++) t += red[w];
        s_usum = t;
    }
    __syncthreads();
    const float usum = s_usum;

    float c = 0.f;
    for (int i = tid; i < VOCAB; i += blockDim.x) {
        float x = 0.1f * th[i] / usum;     // eps * u_v  (always > 0)
        c += x * logf(x);
    }
    c = warp_sum(c);
    __syncthreads();
    if ((tid & 31) == 0) red[tid >> 5] = c;
    __syncthreads();
    if (tid == 0) {
        float t = 0.f;
        for (int w = 0; w < nw; w++) t += red[w];
        g_usum = usum;
        g_C1   = t;
        g_acc  = 0.0;
    }
}

// Persistent kernel: grid = #SMs, each CTA caches token_histo in smem once,
// then processes rows strided by gridDim.x.
__global__ void __launch_bounds__(TPB, 1)
main_kernel(const float* __restrict__ p,
            const int*   __restrict__ dec,
            const float* __restrict__ th) {
    extern __shared__ float sth[];                 // 32000 floats = 128 KB
    __shared__ float red[TPB / 32];

    float4* sth4 = reinterpret_cast<float4*>(sth);
    const float4* th4 = reinterpret_cast<const float4*>(th);
    for (int i = threadIdx.x; i < V4; i += TPB) sth4[i] = th4[i];
    __syncthreads();

    const float usum = g_usum;
    const float C1   = g_C1;
    const int   tid  = threadIdx.x;
    double acc = 0.0;

    for (int row = blockIdx.x; row < NROWS; row += gridDim.x) {
        const int b = row / 1023;
        const int t = row - b * 1023;
        const float* prow = p + (size_t)(b * SEQ + t) * VOCAB;
        const float4* p4 = reinterpret_cast<const float4*>(prow);

        float s0 = 0.f, s1 = 0.f;
        #pragma unroll 5
        for (int k = 0; k < FULL_K; ++k) {
            const int idx = tid + k * TPB;
            float4 v = p4[idx];
            float4 w = sth4[idx];
            s0 = fmaf(w.x, lnfast(v.x), s0);
            s1 = fmaf(w.y, lnfast(v.y), s1);
            s0 = fmaf(w.z, lnfast(v.z), s0);
            s1 = fmaf(w.w, lnfast(v.w), s1);
        }
        if (tid < TAIL_N) {
            const int idx = tid + FULL_K * TPB;
            float4 v = p4[idx];
            float4 w = sth4[idx];
            s0 = fmaf(w.x, lnfast(v.x), s0);
            s1 = fmaf(w.y, lnfast(v.y), s1);
            s0 = fmaf(w.z, lnfast(v.z), s0);
            s1 = fmaf(w.w, lnfast(v.w), s1);
        }

        float s = warp_sum(s0 + s1);
        if ((tid & 31) == 0) red[tid >> 5] = s;
        __syncthreads();
        if (tid == 0) {
            float S = 0.f;
            #pragma unroll
            for (int w = 0; w < TPB / 32; w++) S += red[w];
            const int l = dec[b * SEQ + t + 1];   // labels = dec_input[:,1:]
            if (l != 0) {                          // PAD mask
                float pl = __ldg(prow + l);
                float x  = 0.1f * sth[l] / usum;   // eps * u_label
                float rowv = C1
                           - x * logf(x)
                           + (x + 0.9f) * logf(x + 0.9f)
                           - 0.1f * (S / usum)
                           - 0.9f * logf(pl);
                acc += (double)rowv;
            }
        }
        __syncthreads();   // protect red[] before next row
    }

    if (tid == 0) atomicAdd(&g_acc, acc);
}

__global__ void fin_kernel(float* out) {
    out[0] = (float)(g_acc * (1.0 / (double)NROWS));
}

extern "C" void kernel_launch(void* const* d_in, const int* in_sizes, int n_in,
                              void* d_out, int out_size) {
    // Identify inputs by element count (robust to ordering).
    const int*   dec = nullptr;   // (4,1024) int32
    const float* p   = nullptr;   // (4,1024,32000) fp32
    const float* th  = nullptr;   // (32000,) fp32
    for (int i = 0; i < n_in; ++i) {
        if (in_sizes[i] == 4 * SEQ)       dec = (const int*)d_in[i];
        else if (in_sizes[i] == VOCAB)    th  = (const float*)d_in[i];
        else                              p   = (const float*)d_in[i];
    }

    cudaFuncSetAttribute(main_kernel,
                         cudaFuncAttributeMaxDynamicSharedMemorySize,
                         VOCAB * (int)sizeof(float));

    int sms = 0;
    cudaDeviceGetAttribute(&sms, cudaDevAttrMultiProcessorCount, 0);
    if (sms <= 0) sms = 148;

    prep_kernel<<<1, 1024>>>(th);
    main_kernel<<<sms, TPB, VOCAB * sizeof(float)>>>(p, dec, th);
    fin_kernel<<<1, 1>>>((float*)d_out);
}

// round 2
// speedup vs baseline: 1.2392x; 1.2392x over previous
#include <cuda_runtime.h>
#include <math.h>

#define VOCAB   32000
#define V4      (VOCAB / 4)          // 8000 float4 per row
#define NROWS   4092                 // 4 * 1023
#define SEQ     1024
#define TPB     512
#define FULL_K  (V4 / TPB)           // 15
#define TAIL_N  (V4 - FULL_K * TPB)  // 320
#define MAXCTA  256

__device__ double g_part[MAXCTA];

typedef unsigned long long u64;

// ---------- packed f32x2 helpers ----------
__device__ __forceinline__ u64 pack2(float lo, float hi) {
    u64 r; asm("mov.b64 %0, {%1,%2};" : "=l"(r) : "f"(lo), "f"(hi)); return r;
}
__device__ __forceinline__ void unpack2(u64 v, float& lo, float& hi) {
    asm("mov.b64 {%0,%1}, %2;" : "=f"(lo), "=f"(hi) : "l"(v));
}
__device__ __forceinline__ u64 fma2(u64 a, u64 b, u64 c) {
    u64 d; asm("fma.rn.f32x2 %0, %1, %2, %3;" : "=l"(d) : "l"(a), "l"(b), "l"(c)); return d;
}
__device__ __forceinline__ u64 mul2(u64 a, u64 b) {
    u64 d; asm("mul.rn.f32x2 %0, %1, %2;" : "=l"(d) : "l"(a), "l"(b)); return d;
}
__device__ __forceinline__ u64 add2(u64 a, u64 b) {
    u64 d; asm("add.rn.f32x2 %0, %1, %2;" : "=l"(d) : "l"(a), "l"(b)); return d;
}

// packed constants (two identical fp32 halves)
#define PC(x) ((u64)(x) | ((u64)(x) << 32))
__device__ __forceinline__ void ln_const(u64& cm1, u64& c1, u64& c2, u64& c3,
                                         u64& c4, u64& c5, u64& cln) {
    cm1 = PC(0xBF800000u);  // -1.0
    c1  = PC(0x3F800000u);  //  1.0
    c2  = PC(0xBF000000u);  // -0.5
    c3  = PC(0x3EAAAAABu);  //  1/3
    c4  = PC(0xBE800000u);  // -1/4
    c5  = PC(0x3E4CCCCDu);  //  1/5
    cln = PC(0x33B17218u);  //  ln2 / 2^23
}

// range reduction for a pair: x = m * 2^e, m in [2/3,4/3)
// fm = {m0-1, m1-1}, e2 = {(float)k0, (float)k1}, k = e<<23
__device__ __forceinline__ void lnprep(int i0, int i1, u64 cm1, u64& fm, u64& e2) {
    int k0 = (i0 - 0x3F2AAAAB) & 0xFF800000;
    int k1 = (i1 - 0x3F2AAAAB) & 0xFF800000;
    float f0 = __int_as_float(i0 - k0);
    float f1 = __int_as_float(i1 - k1);
    e2 = pack2((float)k0, (float)k1);
    fm = add2(pack2(f0, f1), cm1);
}

__device__ __forceinline__ float warp_sum(float v) {
    #pragma unroll
    for (int o = 16; o; o >>= 1) v += __shfl_xor_sync(0xFFFFFFFFu, v, o);
    return v;
}
__device__ __forceinline__ double warp_sum_d(double v) {
    #pragma unroll
    for (int o = 16; o; o >>= 1) v += __shfl_xor_sync(0xFFFFFFFFu, v, o);
    return v;
}

__global__ void __launch_bounds__(TPB, 1)
main_kernel(const float* __restrict__ p,
            const int*   __restrict__ dec,
            const float* __restrict__ th) {
    extern __shared__ float sth[];               // 32000 floats = 128 KB
    __shared__ float redf[TPB / 32];
    __shared__ double redd[TPB / 32];
    __shared__ float s_bcast[2];                 // usum, C1

    const int tid = threadIdx.x;
    float4* sth4 = reinterpret_cast<float4*>(sth);
    const float4* th4 = reinterpret_cast<const float4*>(th);
    for (int i = tid; i < V4; i += TPB) sth4[i] = th4[i];
    __syncthreads();

    // ---- per-CTA prologue: usum ----
    {
        float s = 0.f;
        for (int i = tid; i < VOCAB; i += TPB) s += sth[i];
        s = warp_sum(s);
        if ((tid & 31) == 0) redf[tid >> 5] = s;
        __syncthreads();
        if (tid == 0) {
            float t = 0.f;
            #pragma unroll
            for (int w = 0; w < TPB / 32; w++) t += redf[w];
            s_bcast[0] = t;
        }
        __syncthreads();
    }
    const float usum = s_bcast[0];
    const float inv01 = 0.1f / usum;             // eps / usum

    // ---- per-CTA prologue: C1 = sum f(eps*u_v) ----
    {
        float c = 0.f;
        for (int i = tid; i < VOCAB; i += TPB) {
            float x = sth[i] * inv01;
            c += x * logf(x);
        }
        c = warp_sum(c);
        __syncthreads();
        if ((tid & 31) == 0) redf[tid >> 5] = c;
        __syncthreads();
        if (tid == 0) {
            float t = 0.f;
            #pragma unroll
            for (int w = 0; w < TPB / 32; w++) t += redf[w];
            s_bcast[1] = t;
        }
        __syncthreads();
    }
    const float C1 = s_bcast[1];

    double accD = 0.0;

    // ---- label-dependent O(1)-per-row terms: one global thread per row ----
    {
        const int gid = blockIdx.x * TPB + tid;
        if (gid < NROWS) {
            const int b = gid / 1023;
            const int t = gid - b * 1023;
            const int l = __ldg(&dec[b * SEQ + t + 1]);
            if (l != 0) {
                float pl = __ldg(p + (size_t)(b * SEQ + t) * VOCAB + l);
                float x  = sth[l] * inv01;       // eps * u_label
                accD += (double)(C1
                                 - x * logf(x)
                                 + (x + 0.9f) * logf(x + 0.9f)
                                 - 0.9f * logf(pl));
            }
        }
    }

    // ---- bulk: S_row = sum_v th_v * ln p_v, accumulate -eps/usum * S masked ----
    u64 cm1, c1, c2, c3, c4, c5, cln;
    ln_const(cm1, c1, c2, c3, c4, c5, cln);
    const double negScale = -(double)0.1 / (double)usum;

    for (int row = blockIdx.x; row < NROWS; row += gridDim.x) {
        const int b = row / 1023;
        const int t = row - b * 1023;
        const int lbl = __ldg(&dec[b * SEQ + t + 1]);
        const int4* p4 = reinterpret_cast<const int4*>(p + (size_t)(b * SEQ + t) * VOCAB);

        u64 accA = 0, accB = 0;                  // packed {0.f,0.f}
        #pragma unroll 5
        for (int k = 0; k < FULL_K; ++k) {
            const int idx = tid + k * TPB;
            int4   v = p4[idx];
            float4 w = sth4[idx];
            u64 fmA, e2A, fmB, e2B;
            lnprep(v.x, v.y, cm1, fmA, e2A);
            lnprep(v.z, v.w, cm1, fmB, e2B);
            u64 QA = fma2(c5, fmA, c4);
            u64 QB = fma2(c5, fmB, c4);
            QA = fma2(QA, fmA, c3);  QB = fma2(QB, fmB, c3);
            QA = fma2(QA, fmA, c2);  QB = fma2(QB, fmB, c2);
            QA = fma2(QA, fmA, c1);  QB = fma2(QB, fmB, c1);
            u64 LA = fma2(fmA, QA, mul2(e2A, cln));
            u64 LB = fma2(fmB, QB, mul2(e2B, cln));
            accA = fma2(pack2(w.x, w.y), LA, accA);
            accB = fma2(pack2(w.z, w.w), LB, accB);
        }
        if (tid < TAIL_N) {
            const int idx = tid + FULL_K * TPB;
            int4   v = p4[idx];
            float4 w = sth4[idx];
            u64 fmA, e2A, fmB, e2B;
            lnprep(v.x, v.y, cm1, fmA, e2A);
            lnprep(v.z, v.w, cm1, fmB, e2B);
            u64 QA = fma2(c5, fmA, c4);
            u64 QB = fma2(c5, fmB, c4);
            QA = fma2(QA, fmA, c3);  QB = fma2(QB, fmB, c3);
            QA = fma2(QA, fmA, c2);  QB = fma2(QB, fmB, c2);
            QA = fma2(QA, fmA, c1);  QB = fma2(QB, fmB, c1);
            u64 LA = fma2(fmA, QA, mul2(e2A, cln));
            u64 LB = fma2(fmB, QB, mul2(e2B, cln));
            accA = fma2(pack2(w.x, w.y), LA, accA);
            accB = fma2(pack2(w.z, w.w), LB, accB);
        }

        float a0, a1, b0, b1;
        unpack2(accA, a0, a1);
        unpack2(accB, b0, b1);
        float s = warp_sum((a0 + b0) + (a1 + b1));
        if ((tid & 31) == 0 && lbl != 0) accD += (double)s * negScale;
        // no __syncthreads needed: no shared-memory writes in this loop
    }

    // ---- final block reduction (doubles) ----
    accD = warp_sum_d(accD);
    if ((tid & 31) == 0) redd[tid >> 5] = accD;
    __syncthreads();
    if (tid == 0) {
        double t = 0.0;
        #pragma unroll
        for (int w = 0; w < TPB / 32; w++) t += redd[w];
        g_part[blockIdx.x] = t;
    }
}

__global__ void fin_kernel(float* out, int nb) {
    __shared__ double sd[8];
    const int tid = threadIdx.x;
    double v = (tid < nb) ? g_part[tid] : 0.0;
    v = warp_sum_d(v);
    if ((tid & 31) == 0) sd[tid >> 5] = v;
    __syncthreads();
    if (tid == 0) {
        double t = 0.0;
        #pragma unroll
        for (int w = 0; w < 8; w++) t += sd[w];
        out[0] = (float)(t / (double)NROWS);
    }
}

extern "C" void kernel_launch(void* const* d_in, const int* in_sizes, int n_in,
                              void* d_out, int out_size) {
    const int*   dec = nullptr;
    const float* p   = nullptr;
    const float* th  = nullptr;
    for (int i = 0; i < n_in; ++i) {
        if (in_sizes[i] == 4 * SEQ)    dec = (const int*)d_in[i];
        else if (in_sizes[i] == VOCAB) th  = (const float*)d_in[i];
        else                           p   = (const float*)d_in[i];
    }

    cudaFuncSetAttribute(main_kernel,
                         cudaFuncAttributeMaxDynamicSharedMemorySize,
                         VOCAB * (int)sizeof(float));

    int sms = 0;
    cudaDeviceGetAttribute(&sms, cudaDevAttrMultiProcessorCount, 0);
    if (sms <= 0) sms = 148;
    if (sms > MAXCTA) sms = MAXCTA;

    main_kernel<<<sms, TPB, VOCAB * sizeof(float)>>>(p, dec, th);
    fin_kernel<<<1, 256>>>((float*)d_out, sms);
}

// round 4
// speedup vs baseline: 1.5737x; 1.2699x over previous
#include <cuda_runtime.h>
#include <math.h>

#define VOCAB   32000
#define V4      8000                 // float4 per row
#define NROWS   4092                 // 4 * 1023
#define SEQ     1024
#define TPB     1024
#define TAILQ   (V4 - 7 * TPB)       // 832 tail quads (= 26 full warps)
#define MAXCTA  256

__device__ double   g_part[MAXCTA];
__device__ unsigned g_cnt = 0;

typedef unsigned long long u64;

// ---------- packed f32x2 helpers ----------
__device__ __forceinline__ u64 pack2(float lo, float hi) {
    u64 r; asm("mov.b64 %0, {%1,%2};" : "=l"(r) : "f"(lo), "f"(hi)); return r;
}
__device__ __forceinline__ void unpack2(u64 v, float& lo, float& hi) {
    asm("mov.b64 {%0,%1}, %2;" : "=f"(lo), "=f"(hi) : "l"(v));
}
__device__ __forceinline__ u64 fma2(u64 a, u64 b, u64 c) {
    u64 d; asm("fma.rn.f32x2 %0, %1, %2, %3;" : "=l"(d) : "l"(a), "l"(b), "l"(c)); return d;
}
__device__ __forceinline__ u64 mul2(u64 a, u64 b) {
    u64 d; asm("mul.rn.f32x2 %0, %1, %2;" : "=l"(d) : "l"(a), "l"(b)); return d;
}
__device__ __forceinline__ u64 add2(u64 a, u64 b) {
    u64 d; asm("add.rn.f32x2 %0, %1, %2;" : "=l"(d) : "l"(a), "l"(b)); return d;
}

#define PC(x) ((u64)(x) | ((u64)(x) << 32))

// packed log-poly constants
#define K_CM1  PC(0xBF800000u)  // -1.0
#define K_C1   PC(0x3F800000u)  //  1.0
#define K_C2   PC(0xBF000000u)  // -0.5
#define K_C3   PC(0x3EAAAAABu)  //  1/3
#define K_C4   PC(0xBE800000u)  // -1/4
#define K_C5   PC(0x3E4CCCCDu)  //  1/5
#define K_LN2  PC(0x3F317218u)  //  ln 2
#define K_MAG  PC(0xCB400000u)  // -12582912.0f

// scalar fast log (prologue only): degree-5, |abs err| <= 2e-4
__device__ __forceinline__ float lnfast(float x) {
    int i = __float_as_int(x);
    int k = (i - 0x3F2AAAAB) & 0xFF800000;
    float f = __int_as_float(i - k) - 1.0f;
    float P = 0.2f;
    P = fmaf(P, f, -0.25f);
    P = fmaf(P, f,  0.33333334f);
    P = fmaf(P, f, -0.5f);
    P = fmaf(P, f,  1.0f);
    return fmaf(f, P, (float)k * 8.2629582e-8f);
}

__device__ __forceinline__ float warp_sum(float v) {
    #pragma unroll
    for (int o = 16; o; o >>= 1) v += __shfl_xor_sync(0xFFFFFFFFu, v, o);
    return v;
}
__device__ __forceinline__ double warp_sum_d(double v) {
    #pragma unroll
    for (int o = 16; o; o >>= 1) v += __shfl_xor_sync(0xFFFFFFFFu, v, o);
    return v;
}

// packed range reduction, no I2F:
// d = i - C;  k = d & 0xFF800000;  mantissa m = bits(i-k) in [2/3,4/3)
// e = d >> 23;  float(e) exactly via magic-number subtract (exact: small int)
__device__ __forceinline__ void lnprep2(int i0, int i1, u64& fm, u64& fe) {
    int d0 = i0 - 0x3F2AAAAB, d1 = i1 - 0x3F2AAAAB;
    int k0 = d0 & 0xFF800000, k1 = d1 & 0xFF800000;
    float m0 = __int_as_float(i0 - k0);
    float m1 = __int_as_float(i1 - k1);
    int t0 = (d0 >> 23) + 0x4B400000;      // 1.5*2^23 + e
    int t1 = (d1 >> 23) + 0x4B400000;
    fm = add2(pack2(m0, m1), K_CM1);                                   // m - 1
    fe = add2(pack2(__int_as_float(t0), __int_as_float(t1)), K_MAG);   // (float)e exact
}

// process one quad: acc{A,B} += wt * ln(vq)   (pair-packed)
__device__ __forceinline__ void proc_quad(int4 vq, float4 wt, u64& accA, u64& accB) {
    u64 fmA, feA, fmB, feB;
    lnprep2(vq.x, vq.y, fmA, feA);
    lnprep2(vq.z, vq.w, fmB, feB);
    u64 QA = fma2(K_C5, fmA, K_C4);
    u64 QB = fma2(K_C5, fmB, K_C4);
    QA = fma2(QA, fmA, K_C3);  QB = fma2(QB, fmB, K_C3);
    QA = fma2(QA, fmA, K_C2);  QB = fma2(QB, fmB, K_C2);
    QA = fma2(QA, fmA, K_C1);  QB = fma2(QB, fmB, K_C1);
    u64 LA = fma2(fmA, QA, mul2(feA, K_LN2));
    u64 LB = fma2(fmB, QB, mul2(feB, K_LN2));
    accA = fma2(pack2(wt.x, wt.y), LA, accA);
    accB = fma2(pack2(wt.z, wt.w), LB, accB);
}

__global__ void __launch_bounds__(TPB, 1)
main_kernel(const float* __restrict__ p,
            const int*   __restrict__ dec,
            const float* __restrict__ th,
            float* __restrict__ out) {
    extern __shared__ float sth[];               // 32000 floats = 128 KB
    __shared__ float  redf[TPB / 32];
    __shared__ double redd[TPB / 32];
    __shared__ float  s_b[2];
    __shared__ int    s_last;

    const int tid = threadIdx.x;
    float4* sth4 = reinterpret_cast<float4*>(sth);
    const float4* th4 = reinterpret_cast<const float4*>(th);
    for (int i = tid; i < V4; i += TPB) sth4[i] = th4[i];
    __syncthreads();

    // ---- prologue: usum ----
    {
        float s = 0.f;
        for (int i = tid; i < VOCAB; i += TPB) s += sth[i];
        s = warp_sum(s);
        if ((tid & 31) == 0) redf[tid >> 5] = s;
        __syncthreads();
        if (tid == 0) {
            float t = 0.f;
            #pragma unroll
            for (int w = 0; w < TPB / 32; w++) t += redf[w];
            s_b[0] = t;
        }
        __syncthreads();
    }
    const float usum  = s_b[0];
    const float inv01 = 0.1f / usum;             // eps / usum

    // ---- prologue: C1 = sum f(eps*u_v) ----
    {
        float c = 0.f;
        for (int i = tid; i < VOCAB; i += TPB) {
            float x = sth[i] * inv01;
            c += x * lnfast(x);
        }
        c = warp_sum(c);
        if ((tid & 31) == 0) redf[tid >> 5] = c;
        __syncthreads();
        if (tid == 0) {
            float t = 0.f;
            #pragma unroll
            for (int w = 0; w < TPB / 32; w++) t += redf[w];
            s_b[1] = t;
        }
        __syncthreads();
    }
    const float C1 = s_b[1];

    double accD = 0.0;

    // ---- label-dependent O(1)-per-row terms (one global thread per row) ----
    {
        const int gid = blockIdx.x * TPB + tid;
        if (gid < NROWS) {
            const int b = gid / 1023;
            const int t = gid - b * 1023;
            const int l = __ldg(&dec[b * SEQ + t + 1]);
            if (l != 0) {
                float pl = __ldg(p + (size_t)(b * SEQ + t) * VOCAB + l);
                float x  = sth[l] * inv01;
                accD += (double)(C1
                                 - x * logf(x)
                                 + (x + 0.9f) * logf(x + 0.9f)
                                 - 0.9f * logf(pl));
            }
        }
    }

    // ---- bulk: S_row = sum_v th_v * ln p_v ----
    const double negScale = -0.1 / (double)usum;
    const bool   hasTail  = (tid < TAILQ);       // 832 = 26 full warps

    for (int row = blockIdx.x; row < NROWS; row += gridDim.x) {
        const int b = row / 1023;
        const int t = row - b * 1023;
        const int lbl = __ldg(&dec[b * SEQ + t + 1]);
        const int4* p4 = reinterpret_cast<const int4*>(p + (size_t)(b * SEQ + t) * VOCAB);

        u64 accA = 0, accB = 0;

        // batch 1: quads 0..3 (4 LDG.128 in flight)
        {
            int4 v0 = p4[tid];
            int4 v1 = p4[tid + 1 * TPB];
            int4 v2 = p4[tid + 2 * TPB];
            int4 v3 = p4[tid + 3 * TPB];
            float4 w0 = sth4[tid];
            float4 w1 = sth4[tid + 1 * TPB];
            float4 w2 = sth4[tid + 2 * TPB];
            float4 w3 = sth4[tid + 3 * TPB];
            proc_quad(v0, w0, accA, accB);
            proc_quad(v1, w1, accA, accB);
            proc_quad(v2, w2, accA, accB);
            proc_quad(v3, w3, accA, accB);
        }
        // batch 2: quads 4..6 + predicated tail quad (warp-uniform)
        {
            int4 v4 = p4[tid + 4 * TPB];
            int4 v5 = p4[tid + 5 * TPB];
            int4 v6 = p4[tid + 6 * TPB];
            int4 v7;
            if (hasTail) v7 = p4[tid + 7 * TPB];
            float4 w4 = sth4[tid + 4 * TPB];
            float4 w5 = sth4[tid + 5 * TPB];
            float4 w6 = sth4[tid + 6 * TPB];
            proc_quad(v4, w4, accA, accB);
            proc_quad(v5, w5, accA, accB);
            proc_quad(v6, w6, accA, accB);
            if (hasTail) {
                float4 w7 = sth4[tid + 7 * TPB];
                proc_quad(v7, w7, accA, accB);
            }
        }

        float a0, a1, b0, b1;
        unpack2(accA, a0, a1);
        unpack2(accB, b0, b1);
        float s = warp_sum((a0 + b0) + (a1 + b1));
        if ((tid & 31) == 0 && lbl != 0) accD += (double)s * negScale;
    }

    // ---- per-CTA reduction ----
    accD = warp_sum_d(accD);
    if ((tid & 31) == 0) redd[tid >> 5] = accD;
    __syncthreads();
    if (tid == 0) {
        double t = 0.0;
        #pragma unroll
        for (int w = 0; w < TPB / 32; w++) t += redd[w];
        g_part[blockIdx.x] = t;
        __threadfence();
        unsigned old = atomicAdd(&g_cnt, 1u);
        s_last = (old == gridDim.x - 1) ? 1 : 0;
    }
    __syncthreads();

    // ---- last CTA finalizes (no separate fin kernel) ----
    if (s_last) {
        double v = (tid < (int)gridDim.x) ? g_part[tid] : 0.0;
        v = warp_sum_d(v);
        if ((tid & 31) == 0) redd[tid >> 5] = v;
        __syncthreads();
        if (tid == 0) {
            double t = 0.0;
            #pragma unroll
            for (int w = 0; w < TPB / 32; w++) t += redd[w];
            out[0] = (float)(t / (double)NROWS);
            g_cnt = 0;                 // reset for next graph replay
        }
    }
}

extern "C" void kernel_launch(void* const* d_in, const int* in_sizes, int n_in,
                              void* d_out, int out_size) {
    const int*   dec = nullptr;
    const float* p   = nullptr;
    const float* th  = nullptr;
    for (int i = 0; i < n_in; ++i) {
        if (in_sizes[i] == 4 * SEQ)    dec = (const int*)d_in[i];
        else if (in_sizes[i] == VOCAB) th  = (const float*)d_in[i];
        else                           p   = (const float*)d_in[i];
    }

    cudaFuncSetAttribute(main_kernel,
                         cudaFuncAttributeMaxDynamicSharedMemorySize,
                         VOCAB * (int)sizeof(float));

    int sms = 0;
    cudaDeviceGetAttribute(&sms, cudaDevAttrMultiProcessorCount, 0);
    if (sms <= 0) sms = 148;
    if (sms > MAXCTA) sms = MAXCTA;

    main_kernel<<<sms, TPB, VOCAB * sizeof(float)>>>(p, dec, th, (float*)d_out);
}

// round 5
// speedup vs baseline: 1.5748x; 1.0007x over previous
#include <cuda_runtime.h>
#include <math.h>

#define VOCAB   32000
#define V4      8000                 // float4 per row
#define NROWS   4092                 // 4 * 1023
#define SEQ     1024
#define TPB     1024
#define TAILQ   (V4 - 7 * TPB)       // 832 tail quads (= 26 full warps)
#define MAXCTA  256

__device__ double   g_part[MAXCTA];
__device__ unsigned g_cnt = 0;

typedef unsigned long long u64;

// ---------- packed f32x2 helpers ----------
__device__ __forceinline__ u64 pack2(float lo, float hi) {
    u64 r; asm("mov.b64 %0, {%1,%2};" : "=l"(r) : "f"(lo), "f"(hi)); return r;
}
__device__ __forceinline__ void unpack2(u64 v, float& lo, float& hi) {
    asm("mov.b64 {%0,%1}, %2;" : "=f"(lo), "=f"(hi) : "l"(v));
}
__device__ __forceinline__ u64 fma2(u64 a, u64 b, u64 c) {
    u64 d; asm("fma.rn.f32x2 %0, %1, %2, %3;" : "=l"(d) : "l"(a), "l"(b), "l"(c)); return d;
}
__device__ __forceinline__ u64 mul2(u64 a, u64 b) {
    u64 d; asm("mul.rn.f32x2 %0, %1, %2;" : "=l"(d) : "l"(a), "l"(b)); return d;
}
__device__ __forceinline__ u64 add2(u64 a, u64 b) {
    u64 d; asm("add.rn.f32x2 %0, %1, %2;" : "=l"(d) : "l"(a), "l"(b)); return d;
}

#define PC(x) ((u64)(x) | ((u64)(x) << 32))
#define K_CM1  PC(0xBF800000u)  // -1.0
#define K_C1   PC(0x3F800000u)  //  1.0
#define K_C2   PC(0xBF000000u)  // -0.5
#define K_C3   PC(0x3EAAAAABu)  //  1/3
#define K_C4   PC(0xBE800000u)  // -1/4
#define K_C5   PC(0x3E4CCCCDu)  //  1/5
#define K_LN2  PC(0x3F317218u)  //  ln 2
#define K_MAG  PC(0xCB400000u)  // -12582912.0f

// scalar fast log (prologue only): degree-5, |abs err| <= 2e-4
__device__ __forceinline__ float lnfast(float x) {
    int i = __float_as_int(x);
    int k = (i - 0x3F2AAAAB) & 0xFF800000;
    float f = __int_as_float(i - k) - 1.0f;
    float P = 0.2f;
    P = fmaf(P, f, -0.25f);
    P = fmaf(P, f,  0.33333334f);
    P = fmaf(P, f, -0.5f);
    P = fmaf(P, f,  1.0f);
    return fmaf(f, P, (float)k * 8.2629582e-8f);
}

__device__ __forceinline__ float warp_sum(float v) {
    #pragma unroll
    for (int o = 16; o; o >>= 1) v += __shfl_xor_sync(0xFFFFFFFFu, v, o);
    return v;
}
__device__ __forceinline__ double warp_sum_d(double v) {
    #pragma unroll
    for (int o = 16; o; o >>= 1) v += __shfl_xor_sync(0xFFFFFFFFu, v, o);
    return v;
}

// packed range reduction, no I2F (exponent->float via magic-number subtract, exact)
__device__ __forceinline__ void lnprep2(int i0, int i1, u64& fm, u64& fe) {
    int d0 = i0 - 0x3F2AAAAB, d1 = i1 - 0x3F2AAAAB;
    int k0 = d0 & 0xFF800000, k1 = d1 & 0xFF800000;
    float m0 = __int_as_float(i0 - k0);
    float m1 = __int_as_float(i1 - k1);
    int t0 = (d0 >> 23) + 0x4B400000;
    int t1 = (d1 >> 23) + 0x4B400000;
    fm = add2(pack2(m0, m1), K_CM1);
    fe = add2(pack2(__int_as_float(t0), __int_as_float(t1)), K_MAG);
}

// one quad: acc{A,B} += wt * ln(vq)
__device__ __forceinline__ void proc_quad(int4 vq, float4 wt, u64& accA, u64& accB) {
    u64 fmA, feA, fmB, feB;
    lnprep2(vq.x, vq.y, fmA, feA);
    lnprep2(vq.z, vq.w, fmB, feB);
    u64 QA = fma2(K_C5, fmA, K_C4);
    u64 QB = fma2(K_C5, fmB, K_C4);
    QA = fma2(QA, fmA, K_C3);  QB = fma2(QB, fmB, K_C3);
    QA = fma2(QA, fmA, K_C2);  QB = fma2(QB, fmB, K_C2);
    QA = fma2(QA, fmA, K_C1);  QB = fma2(QB, fmB, K_C1);
    u64 LA = fma2(fmA, QA, mul2(feA, K_LN2));
    u64 LB = fma2(fmB, QB, mul2(feB, K_LN2));
    accA = fma2(pack2(wt.x, wt.y), LA, accA);
    accB = fma2(pack2(wt.z, wt.w), LB, accB);
}

// row -> base quad pointer ( b*1024 + t = row + row/1023 )
__device__ __forceinline__ const int4* row_ptr(const float* p, int row) {
    int off = row + row / 1023;
    return reinterpret_cast<const int4*>(p + (size_t)off * VOCAB);
}

__global__ void __launch_bounds__(TPB, 1)
main_kernel(const float* __restrict__ p,
            const int*   __restrict__ dec,
            const float* __restrict__ th,
            float* __restrict__ out) {
    extern __shared__ float sth[];               // 32000 floats = 128 KB
    __shared__ float  redf[TPB / 32];
    __shared__ double redd[TPB / 32];
    __shared__ float  s_b[2];
    __shared__ int    s_last;

    const int tid = threadIdx.x;
    float4* sth4 = reinterpret_cast<float4*>(sth);
    const float4* th4 = reinterpret_cast<const float4*>(th);
    for (int i = tid; i < V4; i += TPB) sth4[i] = th4[i];
    __syncthreads();

    // ---- prologue: usum ----
    {
        float s = 0.f;
        for (int i = tid; i < VOCAB; i += TPB) s += sth[i];
        s = warp_sum(s);
        if ((tid & 31) == 0) redf[tid >> 5] = s;
        __syncthreads();
        if (tid == 0) {
            float t = 0.f;
            #pragma unroll
            for (int w = 0; w < TPB / 32; w++) t += redf[w];
            s_b[0] = t;
        }
        __syncthreads();
    }
    const float usum  = s_b[0];
    const float inv01 = 0.1f / usum;

    // ---- prologue: C1 ----
    {
        float c = 0.f;
        for (int i = tid; i < VOCAB; i += TPB) {
            float x = sth[i] * inv01;
            c += x * lnfast(x);
        }
        c = warp_sum(c);
        if ((tid & 31) == 0) redf[tid >> 5] = c;
        __syncthreads();
        if (tid == 0) {
            float t = 0.f;
            #pragma unroll
            for (int w = 0; w < TPB / 32; w++) t += redf[w];
            s_b[1] = t;
        }
        __syncthreads();
    }
    const float C1 = s_b[1];

    double accD = 0.0;

    // ---- label-dependent O(1)-per-row terms ----
    {
        const int gid = blockIdx.x * TPB + tid;
        if (gid < NROWS) {
            const int b = gid / 1023;
            const int t = gid - b * 1023;
            const int l = __ldg(&dec[b * SEQ + t + 1]);
            if (l != 0) {
                float pl = __ldg(p + (size_t)(b * SEQ + t) * VOCAB + l);
                float x  = sth[l] * inv01;
                accD += (double)(C1
                                 - x * logf(x)
                                 + (x + 0.9f) * logf(x + 0.9f)
                                 - 0.9f * logf(pl));
            }
        }
    }

    // ---- bulk: software-pipelined row loop, no per-row shuffles ----
    const bool hasTail = (tid < TAILQ);
    float thrAcc = 0.f;                          // per-thread masked S accumulator

    int row = blockIdx.x;
    if (row < NROWS) {
        const int4* cp = row_ptr(p, row);
        int4 c0 = cp[tid];
        int4 c1 = cp[tid + 1 * TPB];
        int4 c2 = cp[tid + 2 * TPB];
        int4 c3 = cp[tid + 3 * TPB];

        while (true) {
            // issue tail-half loads of current row
            int4 c4 = cp[tid + 4 * TPB];
            int4 c5 = cp[tid + 5 * TPB];
            int4 c6 = cp[tid + 6 * TPB];
            int4 c7;
            if (hasTail) c7 = cp[tid + 7 * TPB];

            const int b   = row / 1023;
            const int lbl = __ldg(&dec[b * SEQ + (row - b * 1023) + 1]);

            u64 accA = 0, accB = 0;
            proc_quad(c0, sth4[tid          ], accA, accB);
            proc_quad(c1, sth4[tid + 1 * TPB], accA, accB);
            proc_quad(c2, sth4[tid + 2 * TPB], accA, accB);
            proc_quad(c3, sth4[tid + 3 * TPB], accA, accB);

            // prefetch head-half of next row (re-reads current on last iter)
            const int  nrow  = row + gridDim.x;
            const bool valid = (nrow < NROWS);
            const int4* np = valid ? row_ptr(p, nrow) : cp;
            c0 = np[tid];
            c1 = np[tid + 1 * TPB];
            c2 = np[tid + 2 * TPB];
            c3 = np[tid + 3 * TPB];

            proc_quad(c4, sth4[tid + 4 * TPB], accA, accB);
            proc_quad(c5, sth4[tid + 5 * TPB], accA, accB);
            proc_quad(c6, sth4[tid + 6 * TPB], accA, accB);
            if (hasTail) proc_quad(c7, sth4[tid + 7 * TPB], accA, accB);

            float a0, a1, b0, b1;
            unpack2(accA, a0, a1);
            unpack2(accB, b0, b1);
            float rowS = (a0 + b0) + (a1 + b1);
            if (lbl != 0) thrAcc += rowS;

            if (!valid) break;
            row = nrow;
            cp  = np;
        }
    }

    // fold masked S into double accumulator: accD += -eps/usum * thrAcc
    accD += (double)thrAcc * (-0.1 / (double)usum);

    // ---- per-CTA reduction ----
    accD = warp_sum_d(accD);
    if ((tid & 31) == 0) redd[tid >> 5] = accD;
    __syncthreads();
    if (tid == 0) {
        double t = 0.0;
        #pragma unroll
        for (int w = 0; w < TPB / 32; w++) t += redd[w];
        g_part[blockIdx.x] = t;
        __threadfence();
        unsigned old = atomicAdd(&g_cnt, 1u);
        s_last = (old == gridDim.x - 1) ? 1 : 0;
    }
    __syncthreads();

    // ---- last CTA finalizes ----
    if (s_last) {
        double v = (tid < (int)gridDim.x) ? g_part[tid] : 0.0;
        v = warp_sum_d(v);
        if ((tid & 31) == 0) redd[tid >> 5] = v;
        __syncthreads();
        if (tid == 0) {
            double t = 0.0;
            #pragma unroll
            for (int w = 0; w < TPB / 32; w++) t += redd[w];
            out[0] = (float)(t / (double)NROWS);
            g_cnt = 0;                 // reset for next graph replay
        }
    }
}

extern "C" void kernel_launch(void* const* d_in, const int* in_sizes, int n_in,
                              void* d_out, int out_size) {
    const int*   dec = nullptr;
    const float* p   = nullptr;
    const float* th  = nullptr;
    for (int i = 0; i < n_in; ++i) {
        if (in_sizes[i] == 4 * SEQ)    dec = (const int*)d_in[i];
        else if (in_sizes[i] == VOCAB) th  = (const float*)d_in[i];
        else                           p   = (const float*)d_in[i];
    }

    cudaFuncSetAttribute(main_kernel,
                         cudaFuncAttributeMaxDynamicSharedMemorySize,
                         VOCAB * (int)sizeof(float));

    int sms = 0;
    cudaDeviceGetAttribute(&sms, cudaDevAttrMultiProcessorCount, 0);
    if (sms <= 0) sms = 148;
    if (sms > MAXCTA) sms = MAXCTA;

    main_kernel<<<sms, TPB, VOCAB * sizeof(float)>>>(p, dec, th, (float*)d_out);
}